// round 1
// baseline (speedup 1.0000x reference)
#include <cuda_runtime.h>
#include <math.h>

#define HID   16
#define NPIX  131072            // B*H*W = 2*256*256
#define HW    65536
#define EPSF  1e-6f

// ---------------- scratch (static __device__, no allocation) ----------------
__device__ float g_shortcut[NPIX * HID];   // NHWC
__device__ float g_feat0[NPIX * HID];      // NHWC
__device__ float g_n1[NPIX * HID];         // NHWC
__device__ float g_a1[NPIX * HID];         // NHWC
__device__ float g_feat[NPIX * HID];       // NHWC
__device__ float4 g_sig[NPIX];             // (sx, sy, sr, -)

// ---------------- weights in constant memory ----------------
__constant__ float c_pm_w[16], c_pm_b[16], c_pa_w[48], c_pa_b[16], c_n1w[16];
__constant__ float c_fdw_w[144], c_fdw_b[16], c_fpw_w[1200], c_fpw_b[75];
__constant__ float c_cdw_w[144], c_cdw_b[16], c_cpw_w[1200], c_cpw_b[75];
__constant__ float c_n2w[16], c_gate_w[256], c_gate_b[16], c_pout_w[256], c_pout_b[16];
__constant__ float c_sig_w[48], c_sig_b[3], c_off_w[800], c_off_b[50];

// ---------------- helpers ----------------
__device__ __forceinline__ float geluf(float v) {
    return 0.5f * v * (1.0f + erff(v * 0.7071067811865476f));
}
__device__ __forceinline__ float tanh_p(float x) {
    float ax = fabsf(x);
    float e = __expf(2.0f * ax);       // inf for large -> t = 1
    float t = 1.0f - 2.0f / (e + 1.0f);
    return copysignf(t, x);
}
__device__ __forceinline__ float reflectf(float c) {
    c = fmodf(fabsf(c), 510.0f);
    return c > 255.0f ? 510.0f - c : c;
}
__device__ __forceinline__ int reflecti(int i) {
    i = abs(i);
    return i > 255 ? 510 - i : i;
}

struct Tap { int i00, i01, i10, i11; float w00, w01, w10, w11; };

__device__ __forceinline__ Tap mk_tap(float ix, float iy) {
    ix = reflectf(ix);
    iy = reflectf(iy);
    float fx = floorf(ix), fy = floorf(iy);
    float wx = ix - fx, wy = iy - fy;
    int x0 = (int)fx, y0 = (int)fy;
    int x1 = min(x0 + 1, 255), y1 = min(y0 + 1, 255);
    Tap t;
    t.i00 = (y0 << 8) + x0;  t.i01 = (y0 << 8) + x1;
    t.i10 = (y1 << 8) + x0;  t.i11 = (y1 << 8) + x1;
    float omx = 1.0f - wx, omy = 1.0f - wy;
    t.w00 = omx * omy;  t.w01 = wx * omy;
    t.w10 = omx * wy;   t.w11 = wx * wy;
    return t;
}

// ---------------- K1: proj + gelu + rmsnorm ----------------
__global__ void k1_proj(const float* __restrict__ x) {
    int p = blockIdx.x * blockDim.x + threadIdx.x;
    if (p >= NPIX) return;
    int b = p >> 16;
    int hw = p & 0xFFFF;
    const float* xb = x + (size_t)b * 4 * HW;
    float x0 = xb[hw], x1 = xb[HW + hw], x2 = xb[2 * HW + hw], x3 = xb[3 * HW + hw];

    float sc[16], f0[16];
    float ss = 0.0f;
#pragma unroll
    for (int c = 0; c < 16; c++) {
        float v = c_pm_w[c] * x0 + c_pm_b[c] + c_pa_b[c]
                + c_pa_w[c * 3 + 0] * x1 + c_pa_w[c * 3 + 1] * x2 + c_pa_w[c * 3 + 2] * x3;
        sc[c] = v;
        float g = geluf(v);
        f0[c] = g;
        ss += g * g;
    }
    float inv = 1.0f / (sqrtf(ss) * 0.25f + EPSF);

    float* s_ptr = g_shortcut + (size_t)p * 16;
    float* f_ptr = g_feat0 + (size_t)p * 16;
    float* n_ptr = g_n1 + (size_t)p * 16;
#pragma unroll
    for (int c = 0; c < 16; c++) {
        s_ptr[c] = sc[c];
        f_ptr[c] = f0[c];
        n_ptr[c] = f0[c] * inv * c_n1w[c];
    }
}

// ---------------- deform core (M=0 fine, M=1 coarse) ----------------
template <int M>
__device__ __forceinline__ void deform_core(const float* __restrict__ src, int p, float out[16]) {
    const float SPACING = (M == 0) ? 1.0f : 3.0f;
    const float MO      = (M == 0) ? 4.0f : 6.0f;
    int b = p >> 16, y = (p >> 8) & 255, x = p & 255;
    const float* sb = src + ((size_t)b << 16) * 16;

    // depthwise 3x3 (reflect) + bias
    float h[16];
#pragma unroll
    for (int c = 0; c < 16; c++) h[c] = (M == 0 ? c_fdw_b[c] : c_cdw_b[c]);
#pragma unroll
    for (int ky = 0; ky < 3; ky++) {
        int yy = reflecti(y + ky - 1);
#pragma unroll
        for (int kx = 0; kx < 3; kx++) {
            int xx = reflecti(x + kx - 1);
            const float* t = sb + ((size_t)((yy << 8) + xx) << 4);
#pragma unroll
            for (int c = 0; c < 16; c++) {
                float w = (M == 0 ? c_fdw_w[c * 9 + ky * 3 + kx] : c_cdw_w[c * 9 + ky * 3 + kx]);
                h[c] += t[c] * w;
            }
        }
    }
#pragma unroll
    for (int c = 0; c < 16; c++) h[c] = geluf(h[c]);

    // fused pw-conv + softmax-weighted sampling (single pass, no max-sub)
    float acc[16];
#pragma unroll
    for (int c = 0; c < 16; c++) acc[c] = 0.0f;
    float den = 0.0f;

#pragma unroll 1
    for (int k = 0; k < 25; k++) {
        float px = (M == 0 ? c_fpw_b[2 * k]     : c_cpw_b[2 * k]);
        float py = (M == 0 ? c_fpw_b[2 * k + 1] : c_cpw_b[2 * k + 1]);
        float pl = (M == 0 ? c_fpw_b[50 + k]    : c_cpw_b[50 + k]);
#pragma unroll
        for (int c = 0; c < 16; c++) {
            float hv = h[c];
            px += (M == 0 ? c_fpw_w[(2 * k) * 16 + c]     : c_cpw_w[(2 * k) * 16 + c]) * hv;
            py += (M == 0 ? c_fpw_w[(2 * k + 1) * 16 + c] : c_cpw_w[(2 * k + 1) * 16 + c]) * hv;
            pl += (M == 0 ? c_fpw_w[(50 + k) * 16 + c]    : c_cpw_w[(50 + k) * 16 + c]) * hv;
        }
        float dx = SPACING * (float)((k % 5) - 2) + tanh_p(px) * MO;
        float dy = SPACING * (float)((k / 5) - 2) + tanh_p(py) * MO;
        float e = __expf(pl);
        Tap t = mk_tap((float)x + dx, (float)y + dy);
        const float* t00 = sb + ((size_t)t.i00 << 4);
        const float* t01 = sb + ((size_t)t.i01 << 4);
        const float* t10 = sb + ((size_t)t.i10 << 4);
        const float* t11 = sb + ((size_t)t.i11 << 4);
#pragma unroll
        for (int c = 0; c < 16; c++) {
            float s = t.w00 * t00[c] + t.w01 * t01[c] + t.w10 * t10[c] + t.w11 * t11[c];
            acc[c] += e * s;
        }
        den += e;
    }
    float inv = 1.0f / den;
#pragma unroll
    for (int c = 0; c < 16; c++) out[c] = acc[c] * inv;
}

// ---------------- K2: fine deform  (n1 -> a1) ----------------
__global__ void k2_fine() {
    int p = blockIdx.x * blockDim.x + threadIdx.x;
    if (p >= NPIX) return;
    float o[16];
    deform_core<0>(g_n1, p, o);
    float* d = g_a1 + (size_t)p * 16;
#pragma unroll
    for (int c = 0; c < 16; c++) d[c] = o[c];
}

// ---------------- K3: coarse deform + rmsnorm + gate + proj_out + sigma ----------------
__global__ void k3_coarse_tail() {
    int p = blockIdx.x * blockDim.x + threadIdx.x;
    if (p >= NPIX) return;

    float a2[16];
    deform_core<1>(g_a1, p, a2);

    // rmsnorm(a2, norm2)
    float ss = 0.0f;
#pragma unroll
    for (int c = 0; c < 16; c++) ss += a2[c] * a2[c];
    float inv = 1.0f / (sqrtf(ss) * 0.25f + EPSF);
    float t[16];
#pragma unroll
    for (int c = 0; c < 16; c++) t[c] = a2[c] * inv * c_n2w[c];

    // gate conv -> a3, then g = feat0 * a3
    const float* f0p = g_feat0 + (size_t)p * 16;
    float g[16];
#pragma unroll
    for (int o = 0; o < 16; o++) {
        float a3 = c_gate_b[o];
#pragma unroll
        for (int c = 0; c < 16; c++) a3 += c_gate_w[o * 16 + c] * t[c];
        g[o] = f0p[o] * a3;
    }

    // feat = proj_out(g) + b + shortcut
    const float* scp = g_shortcut + (size_t)p * 16;
    float feat[16];
#pragma unroll
    for (int o = 0; o < 16; o++) {
        float v = c_pout_b[o] + scp[o];
#pragma unroll
        for (int c = 0; c < 16; c++) v += c_pout_w[o * 16 + c] * g[c];
        feat[o] = v;
    }
    float* fp = g_feat + (size_t)p * 16;
#pragma unroll
    for (int c = 0; c < 16; c++) fp[c] = feat[c];

    // sigma head: min(softplus(.), 6) + eps
    float sig[3];
#pragma unroll
    for (int j = 0; j < 3; j++) {
        float z = c_sig_b[j];
#pragma unroll
        for (int c = 0; c < 16; c++) z += c_sig_w[j * 16 + c] * feat[c];
        float sp = fmaxf(z, 0.0f) + log1pf(expf(-fabsf(z)));
        sig[j] = fminf(sp, 6.0f) + EPSF;
    }
    g_sig[p] = make_float4(sig[0], sig[1], sig[2], 0.0f);
}

// ---------------- K4: joint bilateral ----------------
__global__ void k4_bilateral(const float* __restrict__ xin, float* __restrict__ out) {
    int p = blockIdx.x * blockDim.x + threadIdx.x;
    if (p >= NPIX) return;
    int b = p >> 16, y = (p >> 8) & 255, x = p & 255;

    float f[16];
    const float* fp = g_feat + (size_t)p * 16;
#pragma unroll
    for (int c = 0; c < 16; c++) f[c] = fp[c];

    float4 s4 = g_sig[p];
    float ax = 0.5f / (s4.x * s4.x);
    float ay = 0.5f / (s4.y * s4.y);
    float ar = 0.5f / (s4.z * s4.z);

    const float* plane = xin + (size_t)b * 4 * HW;          // channel 0 of batch b
    const float* fb = g_feat + ((size_t)b << 16) * 16;

    float num = 0.0f, den = 0.0f;
#pragma unroll 1
    for (int k = 0; k < 25; k++) {
        float px = c_off_b[2 * k], py = c_off_b[2 * k + 1];
#pragma unroll
        for (int c = 0; c < 16; c++) {
            px += c_off_w[(2 * k) * 16 + c] * f[c];
            py += c_off_w[(2 * k + 1) * 16 + c] * f[c];
        }
        float dx = (float)((k % 5) - 2) + tanh_p(px) * 5.0f;
        float dy = (float)((k / 5) - 2) + tanh_p(py) * 5.0f;
        Tap t = mk_tap((float)x + dx, (float)y + dy);

        float patch = t.w00 * plane[t.i00] + t.w01 * plane[t.i01]
                    + t.w10 * plane[t.i10] + t.w11 * plane[t.i11];

        const float* t00 = fb + ((size_t)t.i00 << 4);
        const float* t01 = fb + ((size_t)t.i01 << 4);
        const float* t10 = fb + ((size_t)t.i10 << 4);
        const float* t11 = fb + ((size_t)t.i11 << 4);
        float fd = 0.0f;
#pragma unroll
        for (int c = 0; c < 16; c++) {
            float sv = t.w00 * t00[c] + t.w01 * t01[c] + t.w10 * t10[c] + t.w11 * t11[c];
            float d = f[c] - sv;
            fd += d * d;
        }
        float w = __expf(-(dx * dx * ax + dy * dy * ay) - fd * ar);
        num += patch * w;
        den += w;
    }
    out[p] = num / (den + 1e-8f);
}

// ---------------- launch ----------------
extern "C" void kernel_launch(void* const* d_in, const int* in_sizes, int n_in,
                              void* d_out, int out_size) {
    const float* x = (const float*)d_in[0];

#define CPY(sym, idx, n) cudaMemcpyToSymbolAsync(sym, d_in[idx], (n) * sizeof(float), 0, \
                                                 cudaMemcpyDeviceToDevice, 0)
    CPY(c_pm_w,   1, 16);   CPY(c_pm_b,   2, 16);
    CPY(c_pa_w,   3, 48);   CPY(c_pa_b,   4, 16);
    CPY(c_n1w,    5, 16);
    CPY(c_fdw_w,  6, 144);  CPY(c_fdw_b,  7, 16);
    CPY(c_fpw_w,  8, 1200); CPY(c_fpw_b,  9, 75);
    CPY(c_cdw_w, 10, 144);  CPY(c_cdw_b, 11, 16);
    CPY(c_cpw_w, 12, 1200); CPY(c_cpw_b, 13, 75);
    CPY(c_n2w,   14, 16);
    CPY(c_gate_w,15, 256);  CPY(c_gate_b,16, 16);
    CPY(c_pout_w,17, 256);  CPY(c_pout_b,18, 16);
    CPY(c_sig_w, 19, 48);   CPY(c_sig_b, 20, 3);
    CPY(c_off_w, 21, 800);  CPY(c_off_b, 22, 50);
#undef CPY

    const int TB = 128;
    const int NB = NPIX / TB;
    k1_proj<<<NB, TB>>>(x);
    k2_fine<<<NB, TB>>>();
    k3_coarse_tail<<<NB, TB>>>();
    k4_bilateral<<<NB, TB>>>(x, (float*)d_out);
}

// round 2
// speedup vs baseline: 2.7786x; 2.7786x over previous
#include <cuda_runtime.h>
#include <math.h>

#define HID   16
#define NPIX  131072            // B*H*W = 2*256*256
#define HW    65536
#define EPSF  1e-6f

// ---------------- scratch (static __device__, no allocation) ----------------
// NHWC, 16 channels = 4x float4 per pixel
__device__ float4 g4_short[NPIX * 4];
__device__ float4 g4_feat0[NPIX * 4];
__device__ float4 g4_n1[NPIX * 4];
__device__ float4 g4_a1[NPIX * 4];
__device__ float4 g4_feat[NPIX * 4];
__device__ float4 g_sig[NPIX];             // (sx, sy, sr, -)

// ---------------- weights in constant memory ----------------
__constant__ float c_pm_w[16], c_pm_b[16], c_pa_w[48], c_pa_b[16], c_n1w[16];
__constant__ float c_fdw_w[144], c_fdw_b[16], c_fpw_w[1200], c_fpw_b[75];
__constant__ float c_cdw_w[144], c_cdw_b[16], c_cpw_w[1200], c_cpw_b[75];
__constant__ float c_n2w[16], c_gate_w[256], c_gate_b[16], c_pout_w[256], c_pout_b[16];
__constant__ float c_sig_w[48], c_sig_b[3], c_off_w[800], c_off_b[50];

// ---------------- float4 helpers ----------------
__device__ __forceinline__ float4 f4fma(float a, float4 b, float4 c) {
    return make_float4(fmaf(a, b.x, c.x), fmaf(a, b.y, c.y),
                       fmaf(a, b.z, c.z), fmaf(a, b.w, c.w));
}
__device__ __forceinline__ float4 f4scale(float a, float4 b) {
    return make_float4(a * b.x, a * b.y, a * b.z, a * b.w);
}
__device__ __forceinline__ float f4dot(float4 a, float4 b) {
    return a.x * b.x + a.y * b.y + a.z * b.z + a.w * b.w;
}

// ---------------- scalar helpers ----------------
__device__ __forceinline__ float geluf(float v) {
    return 0.5f * v * (1.0f + erff(v * 0.7071067811865476f));
}
__device__ __forceinline__ float tanh_p(float x) {
    float ax = fabsf(x);
    float e = __expf(2.0f * ax);       // inf for large -> t = 1
    float t = 1.0f - 2.0f / (e + 1.0f);
    return copysignf(t, x);
}
__device__ __forceinline__ float reflectf(float c) {
    c = fmodf(fabsf(c), 510.0f);
    return c > 255.0f ? 510.0f - c : c;
}
__device__ __forceinline__ int reflecti(int i) {
    i = abs(i);
    return i > 255 ? 510 - i : i;
}

struct Tap { int i00, i01, i10, i11; float w00, w01, w10, w11; };

__device__ __forceinline__ Tap mk_tap(float ix, float iy) {
    ix = reflectf(ix);
    iy = reflectf(iy);
    float fx = floorf(ix), fy = floorf(iy);
    float wx = ix - fx, wy = iy - fy;
    int x0 = (int)fx, y0 = (int)fy;
    int x1 = min(x0 + 1, 255), y1 = min(y0 + 1, 255);
    Tap t;
    t.i00 = (y0 << 8) + x0;  t.i01 = (y0 << 8) + x1;
    t.i10 = (y1 << 8) + x0;  t.i11 = (y1 << 8) + x1;
    float omx = 1.0f - wx, omy = 1.0f - wy;
    t.w00 = omx * omy;  t.w01 = wx * omy;
    t.w10 = omx * wy;   t.w11 = wx * wy;
    return t;
}

// bilinear gather of 16 channels (4x float4) from NHWC base
__device__ __forceinline__ void gather16(const float4* __restrict__ fb, const Tap& t,
                                         float4 s[4]) {
    const float4* p00 = fb + ((size_t)t.i00 << 2);
    const float4* p01 = fb + ((size_t)t.i01 << 2);
    const float4* p10 = fb + ((size_t)t.i10 << 2);
    const float4* p11 = fb + ((size_t)t.i11 << 2);
#pragma unroll
    for (int j = 0; j < 4; j++) {
        float4 v = f4scale(t.w00, p00[j]);
        v = f4fma(t.w01, p01[j], v);
        v = f4fma(t.w10, p10[j], v);
        v = f4fma(t.w11, p11[j], v);
        s[j] = v;
    }
}

// ---------------- K1: proj + gelu + rmsnorm ----------------
__global__ void k1_proj(const float* __restrict__ x) {
    int p = blockIdx.x * blockDim.x + threadIdx.x;
    if (p >= NPIX) return;
    int b = p >> 16;
    int hw = p & 0xFFFF;
    const float* xb = x + (size_t)b * 4 * HW;
    float x0 = xb[hw], x1 = xb[HW + hw], x2 = xb[2 * HW + hw], x3 = xb[3 * HW + hw];

    float sc[16], f0[16];
    float ss = 0.0f;
#pragma unroll
    for (int c = 0; c < 16; c++) {
        float v = c_pm_w[c] * x0 + c_pm_b[c] + c_pa_b[c]
                + c_pa_w[c * 3 + 0] * x1 + c_pa_w[c * 3 + 1] * x2 + c_pa_w[c * 3 + 2] * x3;
        sc[c] = v;
        float g = geluf(v);
        f0[c] = g;
        ss += g * g;
    }
    float inv = 1.0f / (sqrtf(ss) * 0.25f + EPSF);

    float4* s_ptr = g4_short + (size_t)p * 4;
    float4* f_ptr = g4_feat0 + (size_t)p * 4;
    float4* n_ptr = g4_n1 + (size_t)p * 4;
#pragma unroll
    for (int j = 0; j < 4; j++) {
        s_ptr[j] = make_float4(sc[4 * j], sc[4 * j + 1], sc[4 * j + 2], sc[4 * j + 3]);
        f_ptr[j] = make_float4(f0[4 * j], f0[4 * j + 1], f0[4 * j + 2], f0[4 * j + 3]);
        n_ptr[j] = make_float4(f0[4 * j] * inv * c_n1w[4 * j],
                               f0[4 * j + 1] * inv * c_n1w[4 * j + 1],
                               f0[4 * j + 2] * inv * c_n1w[4 * j + 2],
                               f0[4 * j + 3] * inv * c_n1w[4 * j + 3]);
    }
}

// ---------------- deform core (M=0 fine, M=1 coarse) ----------------
template <int M>
__device__ __forceinline__ void deform_core(const float4* __restrict__ sb,
                                            int y, int x, float4 out[4]) {
    const float SPACING = (M == 0) ? 1.0f : 3.0f;
    const float MO      = (M == 0) ? 4.0f : 6.0f;

    // depthwise 3x3 (reflect) + bias
    float h[16];
#pragma unroll
    for (int c = 0; c < 16; c++) h[c] = (M == 0 ? c_fdw_b[c] : c_cdw_b[c]);
#pragma unroll
    for (int ky = 0; ky < 3; ky++) {
        int yy = reflecti(y + ky - 1);
#pragma unroll
        for (int kx = 0; kx < 3; kx++) {
            int xx = reflecti(x + kx - 1);
            const float4* t = sb + ((size_t)((yy << 8) + xx) << 2);
#pragma unroll
            for (int j = 0; j < 4; j++) {
                float4 v = t[j];
                int c = 4 * j;
                const float* wb = (M == 0 ? c_fdw_w : c_cdw_w) + ky * 3 + kx;
                h[c + 0] = fmaf(v.x, wb[(c + 0) * 9], h[c + 0]);
                h[c + 1] = fmaf(v.y, wb[(c + 1) * 9], h[c + 1]);
                h[c + 2] = fmaf(v.z, wb[(c + 2) * 9], h[c + 2]);
                h[c + 3] = fmaf(v.w, wb[(c + 3) * 9], h[c + 3]);
            }
        }
    }
#pragma unroll
    for (int c = 0; c < 16; c++) h[c] = geluf(h[c]);

    // fused pw-conv + softmax-weighted sampling (single pass, no max-sub)
    float4 acc[4];
#pragma unroll
    for (int j = 0; j < 4; j++) acc[j] = make_float4(0.f, 0.f, 0.f, 0.f);
    float den = 0.0f;

#pragma unroll 1
    for (int k = 0; k < 25; k++) {
        float px = (M == 0 ? c_fpw_b[2 * k]     : c_cpw_b[2 * k]);
        float py = (M == 0 ? c_fpw_b[2 * k + 1] : c_cpw_b[2 * k + 1]);
        float pl = (M == 0 ? c_fpw_b[50 + k]    : c_cpw_b[50 + k]);
#pragma unroll
        for (int c = 0; c < 16; c++) {
            float hv = h[c];
            px = fmaf((M == 0 ? c_fpw_w[(2 * k) * 16 + c]     : c_cpw_w[(2 * k) * 16 + c]), hv, px);
            py = fmaf((M == 0 ? c_fpw_w[(2 * k + 1) * 16 + c] : c_cpw_w[(2 * k + 1) * 16 + c]), hv, py);
            pl = fmaf((M == 0 ? c_fpw_w[(50 + k) * 16 + c]    : c_cpw_w[(50 + k) * 16 + c]), hv, pl);
        }
        float dx = SPACING * (float)((k % 5) - 2) + tanh_p(px) * MO;
        float dy = SPACING * (float)((k / 5) - 2) + tanh_p(py) * MO;
        float e = __expf(pl);
        Tap t = mk_tap((float)x + dx, (float)y + dy);
        float4 s[4];
        gather16(sb, t, s);
#pragma unroll
        for (int j = 0; j < 4; j++) acc[j] = f4fma(e, s[j], acc[j]);
        den += e;
    }
    float inv = 1.0f / den;
#pragma unroll
    for (int j = 0; j < 4; j++) out[j] = f4scale(inv, acc[j]);
}

// ---------------- K2: fine deform  (n1 -> a1) ----------------
__global__ void k2_fine() {
    int p = blockIdx.x * blockDim.x + threadIdx.x;
    if (p >= NPIX) return;
    int b = p >> 16, y = (p >> 8) & 255, x = p & 255;
    const float4* sb = g4_n1 + (((size_t)b << 16) << 2);
    float4 o[4];
    deform_core<0>(sb, y, x, o);
    float4* d = g4_a1 + (size_t)p * 4;
#pragma unroll
    for (int j = 0; j < 4; j++) d[j] = o[j];
}

// ---------------- K3: coarse deform + rmsnorm + gate + proj_out + sigma ----------------
__global__ void k3_coarse_tail() {
    int p = blockIdx.x * blockDim.x + threadIdx.x;
    if (p >= NPIX) return;
    int b = p >> 16, y = (p >> 8) & 255, x = p & 255;
    const float4* sb = g4_a1 + (((size_t)b << 16) << 2);

    float4 a4[4];
    deform_core<1>(sb, y, x, a4);
    float a2[16];
#pragma unroll
    for (int j = 0; j < 4; j++) {
        a2[4 * j] = a4[j].x; a2[4 * j + 1] = a4[j].y;
        a2[4 * j + 2] = a4[j].z; a2[4 * j + 3] = a4[j].w;
    }

    // rmsnorm(a2, norm2)
    float ss = 0.0f;
#pragma unroll
    for (int c = 0; c < 16; c++) ss += a2[c] * a2[c];
    float inv = 1.0f / (sqrtf(ss) * 0.25f + EPSF);
    float t[16];
#pragma unroll
    for (int c = 0; c < 16; c++) t[c] = a2[c] * inv * c_n2w[c];

    // gate conv -> a3, then g = feat0 * a3
    const float4* f0p = g4_feat0 + (size_t)p * 4;
    float f0v[16];
#pragma unroll
    for (int j = 0; j < 4; j++) {
        float4 v = f0p[j];
        f0v[4 * j] = v.x; f0v[4 * j + 1] = v.y; f0v[4 * j + 2] = v.z; f0v[4 * j + 3] = v.w;
    }
    float g[16];
#pragma unroll
    for (int o = 0; o < 16; o++) {
        float a3 = c_gate_b[o];
#pragma unroll
        for (int c = 0; c < 16; c++) a3 = fmaf(c_gate_w[o * 16 + c], t[c], a3);
        g[o] = f0v[o] * a3;
    }

    // feat = proj_out(g) + b + shortcut
    const float4* scp = g4_short + (size_t)p * 4;
    float scv[16];
#pragma unroll
    for (int j = 0; j < 4; j++) {
        float4 v = scp[j];
        scv[4 * j] = v.x; scv[4 * j + 1] = v.y; scv[4 * j + 2] = v.z; scv[4 * j + 3] = v.w;
    }
    float feat[16];
#pragma unroll
    for (int o = 0; o < 16; o++) {
        float v = c_pout_b[o] + scv[o];
#pragma unroll
        for (int c = 0; c < 16; c++) v = fmaf(c_pout_w[o * 16 + c], g[c], v);
        feat[o] = v;
    }
    float4* fp = g4_feat + (size_t)p * 4;
#pragma unroll
    for (int j = 0; j < 4; j++)
        fp[j] = make_float4(feat[4 * j], feat[4 * j + 1], feat[4 * j + 2], feat[4 * j + 3]);

    // sigma head: min(softplus(.), 6) + eps
    float sig[3];
#pragma unroll
    for (int jj = 0; jj < 3; jj++) {
        float z = c_sig_b[jj];
#pragma unroll
        for (int c = 0; c < 16; c++) z = fmaf(c_sig_w[jj * 16 + c], feat[c], z);
        float sp = fmaxf(z, 0.0f) + log1pf(expf(-fabsf(z)));
        sig[jj] = fminf(sp, 6.0f) + EPSF;
    }
    g_sig[p] = make_float4(sig[0], sig[1], sig[2], 0.0f);
}

// ---------------- K4: joint bilateral ----------------
__global__ void k4_bilateral(const float* __restrict__ xin, float* __restrict__ out) {
    int p = blockIdx.x * blockDim.x + threadIdx.x;
    if (p >= NPIX) return;
    int b = p >> 16, y = (p >> 8) & 255, x = p & 255;

    const float4* fp = g4_feat + (size_t)p * 4;
    float4 fv[4];
    float f[16];
#pragma unroll
    for (int j = 0; j < 4; j++) {
        float4 v = fp[j];
        fv[j] = v;
        f[4 * j] = v.x; f[4 * j + 1] = v.y; f[4 * j + 2] = v.z; f[4 * j + 3] = v.w;
    }

    float4 s4 = g_sig[p];
    float ax = 0.5f / (s4.x * s4.x);
    float ay = 0.5f / (s4.y * s4.y);
    float ar = 0.5f / (s4.z * s4.z);

    const float* plane = xin + (size_t)b * 4 * HW;          // channel 0 of batch b
    const float4* fb = g4_feat + (((size_t)b << 16) << 2);

    float num = 0.0f, den = 0.0f;
#pragma unroll 1
    for (int k = 0; k < 25; k++) {
        float px = c_off_b[2 * k], py = c_off_b[2 * k + 1];
#pragma unroll
        for (int c = 0; c < 16; c++) {
            px = fmaf(c_off_w[(2 * k) * 16 + c], f[c], px);
            py = fmaf(c_off_w[(2 * k + 1) * 16 + c], f[c], py);
        }
        float dx = (float)((k % 5) - 2) + tanh_p(px) * 5.0f;
        float dy = (float)((k / 5) - 2) + tanh_p(py) * 5.0f;
        Tap t = mk_tap((float)x + dx, (float)y + dy);

        float patch = t.w00 * plane[t.i00] + t.w01 * plane[t.i01]
                    + t.w10 * plane[t.i10] + t.w11 * plane[t.i11];

        float4 s[4];
        gather16(fb, t, s);
        float fd = 0.0f;
#pragma unroll
        for (int j = 0; j < 4; j++) {
            float4 d = make_float4(fv[j].x - s[j].x, fv[j].y - s[j].y,
                                   fv[j].z - s[j].z, fv[j].w - s[j].w);
            fd += f4dot(d, d);
        }
        float w = __expf(-(dx * dx * ax + dy * dy * ay) - fd * ar);
        num = fmaf(patch, w, num);
        den += w;
    }
    out[p] = num / (den + 1e-8f);
}

// ---------------- launch ----------------
extern "C" void kernel_launch(void* const* d_in, const int* in_sizes, int n_in,
                              void* d_out, int out_size) {
    const float* x = (const float*)d_in[0];

#define CPY(sym, idx, n) cudaMemcpyToSymbolAsync(sym, d_in[idx], (n) * sizeof(float), 0, \
                                                 cudaMemcpyDeviceToDevice, 0)
    CPY(c_pm_w,   1, 16);   CPY(c_pm_b,   2, 16);
    CPY(c_pa_w,   3, 48);   CPY(c_pa_b,   4, 16);
    CPY(c_n1w,    5, 16);
    CPY(c_fdw_w,  6, 144);  CPY(c_fdw_b,  7, 16);
    CPY(c_fpw_w,  8, 1200); CPY(c_fpw_b,  9, 75);
    CPY(c_cdw_w, 10, 144);  CPY(c_cdw_b, 11, 16);
    CPY(c_cpw_w, 12, 1200); CPY(c_cpw_b, 13, 75);
    CPY(c_n2w,   14, 16);
    CPY(c_gate_w,15, 256);  CPY(c_gate_b,16, 16);
    CPY(c_pout_w,17, 256);  CPY(c_pout_b,18, 16);
    CPY(c_sig_w, 19, 48);   CPY(c_sig_b, 20, 3);
    CPY(c_off_w, 21, 800);  CPY(c_off_b, 22, 50);
#undef CPY

    const int TB = 128;
    const int NB = NPIX / TB;
    k1_proj<<<NB, TB>>>(x);
    k2_fine<<<NB, TB>>>();
    k3_coarse_tail<<<NB, TB>>>();
    k4_bilateral<<<NB, TB>>>(x, (float*)d_out);
}